// round 12
// baseline (speedup 1.0000x reference)
#include <cuda_runtime.h>
#include <math.h>

#define BB 4
#define HH 512
#define WW 512
#define NUM_INST 32
#define EPS 1e-5f
#define MAXB 256

// Ping-pong activation buffers (max 4*16*512*512 floats = 64MB each)
__device__ float g_bufA[BB * 16 * HH * WW];
__device__ float g_bufB[BB * 16 * HH * WW];
// Ping-pong per-(plane,block) stats partials (sum, sumsq)
__device__ float2 g_psA[BB * 256 * MAXB];
__device__ float2 g_psB[BB * 256 * MAXB];
__device__ float g_means[NUM_INST * 3];
__device__ float g_part[NUM_INST * 8 * 4];

__device__ __forceinline__ int refl(int i, int n) {
    return i < 0 ? -i : (i >= n ? 2 * n - 2 - i : i);
}

// ---------------------------------------------------------------------------
// 3x3 stride-2 conv, zero pad 1. InstanceNorm+ReLU fused on the INPUT (stats
// finalized in-block from psIn partials). Fused stats partials on OUTPUT into
// psOut. Thread = TSxTS outputs x COPT channels. Weights in smem via float4.
// TS==2 uses vectorized interior loads (LDG.128 + LDG.32 per footprint row).
// ---------------------------------------------------------------------------
template <int CIN, int COUT, int COPT, int TS, int HIN, int WIN, int NT>
__global__ void __launch_bounds__(NT) conv_s2_t(const float* __restrict__ x,
                                                const float* __restrict__ w,
                                                const float* __restrict__ bias,
                                                float* __restrict__ y,
                                                const float2* __restrict__ psIn,
                                                float2* __restrict__ psOut,
                                                int nblkPrev, float invHW) {
    constexpr int HOUT = HIN / 2, WOUT = WIN / 2;
    constexpr int TW = WOUT / TS;
    constexpr int CHUNK = (CIN < 64) ? CIN : 64;
    constexpr int NX = 2 * TS + 1;
    constexpr int V = COPT / 4;
    __shared__ __align__(16) float wsm[CHUNK * 9 * COPT];
    __shared__ float ssm[NT / 32][COPT], qsm[NT / 32][COPT];
    __shared__ float mnS[CIN], rsS[CIN];

    int t = blockIdx.x * NT + threadIdx.x;
    int cog = blockIdx.y % (COUT / COPT);
    int n = blockIdx.y / (COUT / COPT);
    int oh0 = (t / TW) * TS, ow0 = (t % TW) * TS;
    int lane = threadIdx.x & 31, wrp = threadIdx.x >> 5;

    // Inline finalize of previous layer's stats (deterministic).
    for (int pl = wrp; pl < CIN; pl += NT / 32) {
        float s = 0.f, q = 0.f;
        const float2* pp = psIn + (size_t)(n * CIN + pl) * MAXB;
        for (int i = lane; i < nblkPrev; i += 32) {
            float2 v = pp[i];
            s += v.x;
            q += v.y;
        }
        for (int o = 16; o; o >>= 1) {
            s += __shfl_down_sync(0xffffffffu, s, o);
            q += __shfl_down_sync(0xffffffffu, q, o);
        }
        if (lane == 0) {
            float m = s * invHW;
            float var = q * invHW - m * m;
            mnS[pl] = m;
            rsS[pl] = rsqrtf(var + EPS);
        }
    }
    __syncthreads();

    int iwv[NX]; bool cvl[NX];
#pragma unroll
    for (int c = 0; c < NX; c++) {
        int iw = ow0 * 2 - 1 + c;
        iwv[c] = iw;
        cvl[c] = (unsigned)iw < (unsigned)WIN;
    }
    // interior fast path (columns): whole footprint row is in-bounds
    bool wInt = (ow0 >= 1) && (ow0 * 2 + NX - 2 < WIN);

    float acc[TS * TS * COPT];
#pragma unroll
    for (int i = 0; i < TS * TS * COPT; i++) acc[i] = 0.f;

#pragma unroll 1
    for (int c0 = 0; c0 < CIN; c0 += CHUNK) {
        __syncthreads();
        for (int i = threadIdx.x; i < CHUNK * 9 * COPT; i += NT) {
            int ci_l = i / (9 * COPT);
            int rem = i - ci_l * (9 * COPT);
            int tap = rem / COPT;
            int u = rem - tap * COPT;
            wsm[i] = w[((size_t)(cog * COPT + u) * CIN + c0 + ci_l) * 9 + tap];
        }
        __syncthreads();
#pragma unroll 1
        for (int ci_l = 0; ci_l < CHUNK; ci_l++) {
            int ci = c0 + ci_l;
            const float* xp = x + (size_t)(n * CIN + ci) * HIN * WIN;
            float rs = rsS[ci];
            float nb = -mnS[ci] * rs;
#pragma unroll 1
            for (int r = 0; r < NX; r++) {
                int ih = oh0 * 2 - 1 + r;
                bool rv = (unsigned)ih < (unsigned)HIN;
                const float* xr = xp + (size_t)ih * WIN;
                float xv[NX];
                if (TS == 2 && rv && wInt) {
                    const float* base = xr + ow0 * 2;   // 16B-aligned (ow0 even)
                    float x0 = base[-1];
                    float4 q4 = *reinterpret_cast<const float4*>(base);
                    xv[0] = x0;
                    xv[1] = q4.x; xv[2] = q4.y; xv[3] = q4.z;
                    if (NX > 4) xv[4] = q4.w;
#pragma unroll
                    for (int c = 0; c < NX; c++) xv[c] = fmaxf(fmaf(xv[c], rs, nb), 0.f);
                } else {
#pragma unroll
                    for (int c = 0; c < NX; c++) {
                        bool v = rv && cvl[c];
                        float raw = v ? xr[iwv[c]] : 0.f;
                        xv[c] = v ? fmaxf(fmaf(raw, rs, nb), 0.f) : 0.f;
                    }
                }
#pragma unroll
                for (int orow = 0; orow < TS; orow++) {
                    int kh = r - 2 * orow;
                    if (kh >= 0 && kh < 3) {
                        const float4* wp4 =
                            reinterpret_cast<const float4*>(wsm + (ci_l * 9 + kh * 3) * COPT);
#pragma unroll
                        for (int kw = 0; kw < 3; kw++) {
#pragma unroll
                            for (int v = 0; v < V; v++) {
                                float4 wq = wp4[kw * V + v];
                                float wa[4] = {wq.x, wq.y, wq.z, wq.w};
#pragma unroll
                                for (int j = 0; j < 4; j++) {
#pragma unroll
                                    for (int oc = 0; oc < TS; oc++)
                                        acc[(orow * TS + oc) * COPT + v * 4 + j] =
                                            fmaf(xv[2 * oc + kw], wa[j],
                                                 acc[(orow * TS + oc) * COPT + v * 4 + j]);
                                }
                            }
                        }
                    }
                }
            }
        }
    }
    // bias
#pragma unroll
    for (int u = 0; u < COPT; u++) {
        float bv = bias[cog * COPT + u];
#pragma unroll
        for (int p = 0; p < TS * TS; p++) acc[p * COPT + u] += bv;
    }
    // stores
    size_t obase = (size_t)(n * COUT + cog * COPT) * HOUT * WOUT + (size_t)oh0 * WOUT + ow0;
#pragma unroll
    for (int u = 0; u < COPT; u++) {
#pragma unroll
        for (int orow = 0; orow < TS; orow++) {
            float* yp = y + obase + (size_t)u * HOUT * WOUT + (size_t)orow * WOUT;
            if (TS == 4) {
                float4 v;
                v.x = acc[(orow * TS + 0) * COPT + u];
                v.y = acc[(orow * TS + 1) * COPT + u];
                v.z = acc[(orow * TS + 2) * COPT + u];
                v.w = acc[(orow * TS + 3) * COPT + u];
                *reinterpret_cast<float4*>(yp) = v;
            } else {
                float2 v;
                v.x = acc[(orow * TS + 0) * COPT + u];
                v.y = acc[(orow * TS + 1) * COPT + u];
                *reinterpret_cast<float2*>(yp) = v;
            }
        }
    }
    // fused stats partial (deterministic)
#pragma unroll
    for (int u = 0; u < COPT; u++) {
        float s = 0.f, q = 0.f;
#pragma unroll
        for (int p = 0; p < TS * TS; p++) {
            float v = acc[p * COPT + u];
            s += v;
            q += v * v;
        }
        for (int o = 16; o; o >>= 1) {
            s += __shfl_down_sync(0xffffffffu, s, o);
            q += __shfl_down_sync(0xffffffffu, q, o);
        }
        if (lane == 0) { ssm[wrp][u] = s; qsm[wrp][u] = q; }
    }
    __syncthreads();
    if (threadIdx.x < COPT) {
        float s = 0.f, q = 0.f;
#pragma unroll
        for (int wpp = 0; wpp < NT / 32; wpp++) { s += ssm[wpp][threadIdx.x]; q += qsm[wpp][threadIdx.x]; }
        int plane = n * COUT + cog * COPT + threadIdx.x;
        psOut[(size_t)plane * MAXB + blockIdx.x] = make_float2(s, q);
    }
}

// ---------------------------------------------------------------------------
// ConvTranspose2d k=3 s=2 p=1 op=1, fused norm+relu on input (inline stats),
// fused stats on output. Weight layout (CIN, COUT, 3, 3).
// ---------------------------------------------------------------------------
template <int CIN, int COUT, int COPT, int TS, int HIN, int WIN, int NT>
__global__ void __launch_bounds__(NT) deconv_t(const float* __restrict__ x,
                                               const float* __restrict__ w,
                                               const float* __restrict__ bias,
                                               float* __restrict__ y,
                                               const float2* __restrict__ psIn,
                                               float2* __restrict__ psOut,
                                               int nblkPrev, float invHW) {
    constexpr int HOUT = HIN * 2, WOUT = WIN * 2;
    constexpr int TW = WOUT / TS;
    constexpr int SUB = TS / 2;
    constexpr int CHUNK = (CIN < 64) ? CIN : 64;
    constexpr int V = COPT / 4;
    __shared__ __align__(16) float wsm[CHUNK * 9 * COPT];
    __shared__ float ssm[NT / 32][COPT], qsm[NT / 32][COPT];
    __shared__ float mnS[CIN], rsS[CIN];

    int t = blockIdx.x * NT + threadIdx.x;
    int cog = blockIdx.y % (COUT / COPT);
    int n = blockIdx.y / (COUT / COPT);
    int oh0 = (t / TW) * TS, ow0 = (t % TW) * TS;
    int i0 = oh0 >> 1, j0 = ow0 >> 1;
    int lane = threadIdx.x & 31, wrp = threadIdx.x >> 5;

    for (int pl = wrp; pl < CIN; pl += NT / 32) {
        float s = 0.f, q = 0.f;
        const float2* pp = psIn + (size_t)(n * CIN + pl) * MAXB;
        for (int i = lane; i < nblkPrev; i += 32) {
            float2 v = pp[i];
            s += v.x;
            q += v.y;
        }
        for (int o = 16; o; o >>= 1) {
            s += __shfl_down_sync(0xffffffffu, s, o);
            q += __shfl_down_sync(0xffffffffu, q, o);
        }
        if (lane == 0) {
            float m = s * invHW;
            float var = q * invHW - m * m;
            mnS[pl] = m;
            rsS[pl] = rsqrtf(var + EPS);
        }
    }
    __syncthreads();

    float acc[TS * TS * COPT];
#pragma unroll
    for (int i = 0; i < TS * TS * COPT; i++) acc[i] = 0.f;

#pragma unroll 1
    for (int c0 = 0; c0 < CIN; c0 += CHUNK) {
        __syncthreads();
        for (int i = threadIdx.x; i < CHUNK * 9 * COPT; i += NT) {
            int ci_l = i / (9 * COPT);
            int rem = i - ci_l * (9 * COPT);
            int tap = rem / COPT;
            int u = rem - tap * COPT;
            wsm[i] = w[((size_t)(c0 + ci_l) * COUT + cog * COPT + u) * 9 + tap];
        }
        __syncthreads();
#pragma unroll 1
        for (int ci_l = 0; ci_l < CHUNK; ci_l++) {
            int ci = c0 + ci_l;
            const float* xp = x + (size_t)(n * CIN + ci) * HIN * WIN;
            float rs = rsS[ci];
            float nb = -mnS[ci] * rs;
            float xr[(SUB + 1) * (SUB + 1)];
#pragma unroll
            for (int r = 0; r <= SUB; r++) {
                bool rv = (i0 + r) < HIN;
                const float* xpr = xp + (size_t)(i0 + r) * WIN;
#pragma unroll
                for (int c = 0; c <= SUB; c++) {
                    bool v = rv && (j0 + c) < WIN;
                    float raw = v ? xpr[j0 + c] : 0.f;
                    xr[r * (SUB + 1) + c] = v ? fmaxf(fmaf(raw, rs, nb), 0.f) : 0.f;
                }
            }
#pragma unroll
            for (int kh = 0; kh < 3; kh++) {
                int orl = (kh == 1) ? 0 : 1;
                int xro = (kh == 0) ? 1 : 0;
#pragma unroll
                for (int kw = 0; kw < 3; kw++) {
                    int ocl = (kw == 1) ? 0 : 1;
                    int xco = (kw == 0) ? 1 : 0;
                    const float4* wp4 =
                        reinterpret_cast<const float4*>(wsm + (ci_l * 9 + kh * 3 + kw) * COPT);
#pragma unroll
                    for (int v = 0; v < V; v++) {
                        float4 wq = wp4[v];
                        float wa[4] = {wq.x, wq.y, wq.z, wq.w};
#pragma unroll
                        for (int j = 0; j < 4; j++) {
#pragma unroll
                            for (int a = 0; a < SUB; a++)
#pragma unroll
                                for (int b = 0; b < SUB; b++)
                                    acc[((2 * a + orl) * TS + (2 * b + ocl)) * COPT + v * 4 + j] =
                                        fmaf(xr[(a + xro) * (SUB + 1) + (b + xco)], wa[j],
                                             acc[((2 * a + orl) * TS + (2 * b + ocl)) * COPT + v * 4 + j]);
                        }
                    }
                }
            }
        }
    }
#pragma unroll
    for (int u = 0; u < COPT; u++) {
        float bv = bias[cog * COPT + u];
#pragma unroll
        for (int p = 0; p < TS * TS; p++) acc[p * COPT + u] += bv;
    }
    size_t obase = (size_t)(n * COUT + cog * COPT) * HOUT * WOUT + (size_t)oh0 * WOUT + ow0;
#pragma unroll
    for (int u = 0; u < COPT; u++) {
#pragma unroll
        for (int orow = 0; orow < TS; orow++) {
            float* yp = y + obase + (size_t)u * HOUT * WOUT + (size_t)orow * WOUT;
            if (TS == 4) {
                float4 v;
                v.x = acc[(orow * TS + 0) * COPT + u];
                v.y = acc[(orow * TS + 1) * COPT + u];
                v.z = acc[(orow * TS + 2) * COPT + u];
                v.w = acc[(orow * TS + 3) * COPT + u];
                *reinterpret_cast<float4*>(yp) = v;
            } else {
                float2 v;
                v.x = acc[(orow * TS + 0) * COPT + u];
                v.y = acc[(orow * TS + 1) * COPT + u];
                *reinterpret_cast<float2*>(yp) = v;
            }
        }
    }
#pragma unroll
    for (int u = 0; u < COPT; u++) {
        float s = 0.f, q = 0.f;
#pragma unroll
        for (int p = 0; p < TS * TS; p++) {
            float v = acc[p * COPT + u];
            s += v;
            q += v * v;
        }
        for (int o = 16; o; o >>= 1) {
            s += __shfl_down_sync(0xffffffffu, s, o);
            q += __shfl_down_sync(0xffffffffu, q, o);
        }
        if (lane == 0) { ssm[wrp][u] = s; qsm[wrp][u] = q; }
    }
    __syncthreads();
    if (threadIdx.x < COPT) {
        float s = 0.f, q = 0.f;
#pragma unroll
        for (int wpp = 0; wpp < NT / 32; wpp++) { s += ssm[wpp][threadIdx.x]; q += qsm[wpp][threadIdx.x]; }
        int plane = n * COUT + cog * COPT + threadIdx.x;
        psOut[(size_t)plane * MAXB + blockIdx.x] = make_float2(s, q);
    }
}

// ---------------------------------------------------------------------------
// conv0: reflect-pad 3, 7x7, 3->16. Thread = 1 row x 4 cols, all 16 co.
// Interior threads use 3x LDG.128 for the 10-wide footprint row.
// ---------------------------------------------------------------------------
__global__ void __launch_bounds__(256) conv7_first(const float* __restrict__ x,
                                                   const float* __restrict__ w,
                                                   const float* __restrict__ bias,
                                                   float* __restrict__ y,
                                                   float2* __restrict__ psOut) {
    __shared__ __align__(16) float wsm[3 * 49 * 16];
    __shared__ float ssm[8][16], qsm[8][16];
    for (int i = threadIdx.x; i < 3 * 49 * 16; i += 256) {
        int ci = i / (49 * 16);
        int rem = i - ci * (49 * 16);
        int tap = rem / 16;
        int co = rem - tap * 16;
        wsm[i] = w[(co * 3 + ci) * 49 + tap];
    }
    __syncthreads();

    int t = blockIdx.x * 256 + threadIdx.x;
    int n = blockIdx.y;
    int oh = t >> 7;               // 128 threads per row, 4 px each
    int ow0 = (t & 127) * 4;

    int iwI[10];
#pragma unroll
    for (int c = 0; c < 10; c++) iwI[c] = refl(ow0 - 3 + c, WW);
    bool wInt = (ow0 >= 4) && (ow0 + 7 <= WW - 1);

    float acc[4 * 16];
#pragma unroll
    for (int i = 0; i < 4 * 16; i++) acc[i] = 0.f;

#pragma unroll 1
    for (int ci = 0; ci < 3; ci++) {
        const float* xp = x + (size_t)(n * 3 + ci) * HH * WW;
#pragma unroll 1
        for (int kh = 0; kh < 7; kh++) {
            const float* xr = xp + (size_t)refl(oh + kh - 3, HH) * WW;
            float xv[10];
            if (wInt) {
                const float* b = xr + ow0;
                float4 qa = *reinterpret_cast<const float4*>(b - 4);
                float4 qb = *reinterpret_cast<const float4*>(b);
                float4 qc = *reinterpret_cast<const float4*>(b + 4);
                xv[0] = qa.y; xv[1] = qa.z; xv[2] = qa.w;
                xv[3] = qb.x; xv[4] = qb.y; xv[5] = qb.z; xv[6] = qb.w;
                xv[7] = qc.x; xv[8] = qc.y; xv[9] = qc.z;
            } else {
#pragma unroll
                for (int c = 0; c < 10; c++) xv[c] = xr[iwI[c]];
            }
            const float4* wb4 = reinterpret_cast<const float4*>(wsm + (ci * 49 + kh * 7) * 16);
#pragma unroll
            for (int kw = 0; kw < 7; kw++) {
#pragma unroll
                for (int v = 0; v < 4; v++) {
                    float4 wq = wb4[kw * 4 + v];
                    float wa[4] = {wq.x, wq.y, wq.z, wq.w};
#pragma unroll
                    for (int j = 0; j < 4; j++) {
#pragma unroll
                        for (int sc = 0; sc < 4; sc++)
                            acc[sc * 16 + v * 4 + j] = fmaf(xv[sc + kw], wa[j], acc[sc * 16 + v * 4 + j]);
                    }
                }
            }
        }
    }
#pragma unroll
    for (int co = 0; co < 16; co++) {
        float bv = bias[co];
#pragma unroll
        for (int sc = 0; sc < 4; sc++) acc[sc * 16 + co] += bv;
    }
#pragma unroll
    for (int co = 0; co < 16; co++) {
        float* yp = y + (size_t)(n * 16 + co) * HH * WW + (size_t)oh * WW + ow0;
        float4 v0;
        v0.x = acc[0 * 16 + co]; v0.y = acc[1 * 16 + co];
        v0.z = acc[2 * 16 + co]; v0.w = acc[3 * 16 + co];
        *reinterpret_cast<float4*>(yp) = v0;
    }
    int lane = threadIdx.x & 31, wrp = threadIdx.x >> 5;
#pragma unroll
    for (int co = 0; co < 16; co++) {
        float s = 0.f, q = 0.f;
#pragma unroll
        for (int sc = 0; sc < 4; sc++) {
            float v = acc[sc * 16 + co];
            s += v;
            q += v * v;
        }
        for (int o = 16; o; o >>= 1) {
            s += __shfl_down_sync(0xffffffffu, s, o);
            q += __shfl_down_sync(0xffffffffu, q, o);
        }
        if (lane == 0) { ssm[wrp][co] = s; qsm[wrp][co] = q; }
    }
    __syncthreads();
    if (threadIdx.x < 16) {
        float s = 0.f, q = 0.f;
#pragma unroll
        for (int wpp = 0; wpp < 8; wpp++) { s += ssm[wpp][threadIdx.x]; q += qsm[wpp][threadIdx.x]; }
        int plane = n * 16 + threadIdx.x;
        psOut[(size_t)plane * MAXB + blockIdx.x] = make_float2(s, q);
    }
}

// ---------------------------------------------------------------------------
// conv9: reflect-pad 3, 7x7, 16->3, inline-stats norm+relu on input, tanh out.
// Interior threads use 4x LDG.128 for the 14-wide footprint row.
// ---------------------------------------------------------------------------
__global__ void __launch_bounds__(256) conv7_last(const float* __restrict__ x,
                                                  const float* __restrict__ w,
                                                  const float* __restrict__ bias,
                                                  float* __restrict__ y,
                                                  const float2* __restrict__ psIn,
                                                  int nblkPrev, float invHW) {
    __shared__ float wsm[16 * 49 * 3];
    __shared__ float mnS[16], rsS[16];
    for (int i = threadIdx.x; i < 16 * 49 * 3; i += 256) {
        int ci = i / (49 * 3);
        int rem = i - ci * (49 * 3);
        int tap = rem / 3;
        int co = rem - tap * 3;
        wsm[i] = w[(co * 16 + ci) * 49 + tap];
    }
    int lane = threadIdx.x & 31, wrp = threadIdx.x >> 5;
    int n = blockIdx.y;
    for (int pl = wrp; pl < 16; pl += 8) {
        float s = 0.f, q = 0.f;
        const float2* pp = psIn + (size_t)(n * 16 + pl) * MAXB;
        for (int i = lane; i < nblkPrev; i += 32) {
            float2 v = pp[i];
            s += v.x;
            q += v.y;
        }
        for (int o = 16; o; o >>= 1) {
            s += __shfl_down_sync(0xffffffffu, s, o);
            q += __shfl_down_sync(0xffffffffu, q, o);
        }
        if (lane == 0) {
            float m = s * invHW;
            float var = q * invHW - m * m;
            mnS[pl] = m;
            rsS[pl] = rsqrtf(var + EPS);
        }
    }
    __syncthreads();

    int t = blockIdx.x * 256 + threadIdx.x;
    int oh = t >> 6;
    int ow0 = (t & 63) * 8;

    int iwI[14];
#pragma unroll
    for (int c = 0; c < 14; c++) iwI[c] = refl(ow0 - 3 + c, WW);
    bool wInt = (ow0 >= 8) && (ow0 + 11 <= WW - 1);

    float acc[8 * 3];
#pragma unroll
    for (int i = 0; i < 8 * 3; i++) acc[i] = 0.f;

#pragma unroll 1
    for (int ci = 0; ci < 16; ci++) {
        const float* xp = x + (size_t)(n * 16 + ci) * HH * WW;
        float rs = rsS[ci];
        float nb = -mnS[ci] * rs;
#pragma unroll 1
        for (int kh = 0; kh < 7; kh++) {
            const float* xr = xp + (size_t)refl(oh + kh - 3, HH) * WW;
            float xv[14];
            if (wInt) {
                const float* b = xr + ow0;
                float4 qa = *reinterpret_cast<const float4*>(b - 4);
                float4 qb = *reinterpret_cast<const float4*>(b);
                float4 qc = *reinterpret_cast<const float4*>(b + 4);
                float4 qd = *reinterpret_cast<const float4*>(b + 8);
                xv[0] = qa.y;  xv[1] = qa.z;  xv[2] = qa.w;
                xv[3] = qb.x;  xv[4] = qb.y;  xv[5] = qb.z;  xv[6] = qb.w;
                xv[7] = qc.x;  xv[8] = qc.y;  xv[9] = qc.z;  xv[10] = qc.w;
                xv[11] = qd.x; xv[12] = qd.y; xv[13] = qd.z;
            } else {
#pragma unroll
                for (int c = 0; c < 14; c++) xv[c] = xr[iwI[c]];
            }
#pragma unroll
            for (int c = 0; c < 14; c++) xv[c] = fmaxf(fmaf(xv[c], rs, nb), 0.f);
            const float* wb = wsm + (ci * 49 + kh * 7) * 3;
#pragma unroll
            for (int kw = 0; kw < 7; kw++) {
#pragma unroll
                for (int co = 0; co < 3; co++) {
                    float wvv = wb[kw * 3 + co];
#pragma unroll
                    for (int sc = 0; sc < 8; sc++)
                        acc[sc * 3 + co] = fmaf(xv[sc + kw], wvv, acc[sc * 3 + co]);
                }
            }
        }
    }
#pragma unroll
    for (int co = 0; co < 3; co++) {
        float bv = bias[co];
        float* yp = y + (size_t)(n * 3 + co) * HH * WW + (size_t)oh * WW + ow0;
        float4 v0, v1;
        v0.x = tanhf(acc[0 * 3 + co] + bv); v0.y = tanhf(acc[1 * 3 + co] + bv);
        v0.z = tanhf(acc[2 * 3 + co] + bv); v0.w = tanhf(acc[3 * 3 + co] + bv);
        v1.x = tanhf(acc[4 * 3 + co] + bv); v1.y = tanhf(acc[5 * 3 + co] + bv);
        v1.z = tanhf(acc[6 * 3 + co] + bv); v1.w = tanhf(acc[7 * 3 + co] + bv);
        ((float4*)yp)[0] = v0;
        ((float4*)yp)[1] = v1;
    }
}

// ---------------------------------------------------------------------------
// Segment mean: (label, slice) partials, deterministic, then combine.
// ---------------------------------------------------------------------------
__global__ void segpart_k(const float* __restrict__ feats, const int* __restrict__ inst) {
    int lab = blockIdx.x, slice = blockIdx.y;
    const int HWp = HH * WW;
    const int per = BB * HWp / 8;
    int start = slice * per;
    float c0 = 0.f, c1 = 0.f, c2 = 0.f, cnt = 0.f;
    for (int p = start + threadIdx.x; p < start + per; p += 256) {
        if (inst[p] == lab) {
            int n = p / HWp;
            int hw = p - n * HWp;
            const float* f = feats + (size_t)n * 3 * HWp + hw;
            c0 += f[0];
            c1 += f[HWp];
            c2 += f[2 * HWp];
            cnt += 1.f;
        }
    }
    __shared__ float s0[256], s1[256], s2[256], sc[256];
    s0[threadIdx.x] = c0; s1[threadIdx.x] = c1; s2[threadIdx.x] = c2; sc[threadIdx.x] = cnt;
    __syncthreads();
    for (int o = 128; o > 0; o >>= 1) {
        if (threadIdx.x < o) {
            s0[threadIdx.x] += s0[threadIdx.x + o];
            s1[threadIdx.x] += s1[threadIdx.x + o];
            s2[threadIdx.x] += s2[threadIdx.x + o];
            sc[threadIdx.x] += sc[threadIdx.x + o];
        }
        __syncthreads();
    }
    if (threadIdx.x == 0) {
        float* q = &g_part[(lab * 8 + slice) * 4];
        q[0] = s0[0]; q[1] = s1[0]; q[2] = s2[0]; q[3] = sc[0];
    }
}

__global__ void segfin_k() {
    int lab = threadIdx.x;
    if (lab >= NUM_INST) return;
    float s0 = 0.f, s1 = 0.f, s2 = 0.f, c = 0.f;
    for (int sl = 0; sl < 8; sl++) {
        const float* p = &g_part[(lab * 8 + sl) * 4];
        s0 += p[0]; s1 += p[1]; s2 += p[2]; c += p[3];
    }
    float d = fmaxf(c, 1.f);
    g_means[lab * 3 + 0] = s0 / d;
    g_means[lab * 3 + 1] = s1 / d;
    g_means[lab * 3 + 2] = s2 / d;
}

__global__ void gather_k(const int* __restrict__ inst, float* __restrict__ out) {
    int idx = blockIdx.x * 256 + threadIdx.x;
    const int Q = HH * WW / 4;
    if (idx >= BB * Q) return;
    int n = idx / Q, h4 = idx - n * Q;
    int4 lb = ((const int4*)inst)[(size_t)n * Q + h4];
#pragma unroll
    for (int c = 0; c < 3; c++) {
        float4 v;
        v.x = g_means[lb.x * 3 + c];
        v.y = g_means[lb.y * 3 + c];
        v.z = g_means[lb.z * 3 + c];
        v.w = g_means[lb.w * 3 + c];
        ((float4*)out)[(size_t)(n * 3 + c) * Q + h4] = v;
    }
}

// ---------------------------------------------------------------------------
extern "C" void kernel_launch(void* const* d_in, const int* in_sizes, int n_in,
                              void* d_out, int out_size) {
    const float* input = (const float*)d_in[0];
    const int* inst = (const int*)d_in[1];
    const float* w0 = (const float*)d_in[2];  const float* b0 = (const float*)d_in[3];
    const float* w1 = (const float*)d_in[4];  const float* b1 = (const float*)d_in[5];
    const float* w2 = (const float*)d_in[6];  const float* b2 = (const float*)d_in[7];
    const float* w3 = (const float*)d_in[8];  const float* b3 = (const float*)d_in[9];
    const float* w4 = (const float*)d_in[10]; const float* b4 = (const float*)d_in[11];
    const float* w5 = (const float*)d_in[12]; const float* b5 = (const float*)d_in[13];
    const float* w6 = (const float*)d_in[14]; const float* b6 = (const float*)d_in[15];
    const float* w7 = (const float*)d_in[16]; const float* b7 = (const float*)d_in[17];
    const float* w8 = (const float*)d_in[18]; const float* b8 = (const float*)d_in[19];
    const float* w9 = (const float*)d_in[20]; const float* b9 = (const float*)d_in[21];
    float* out = (float*)d_out;

    float* bufA;
    float* bufB;
    float2* psA;
    float2* psB;
    cudaGetSymbolAddress((void**)&bufA, g_bufA);
    cudaGetSymbolAddress((void**)&bufB, g_bufB);
    cudaGetSymbolAddress((void**)&psA, g_psA);
    cudaGetSymbolAddress((void**)&psB, g_psB);

    const float i512 = 1.f / (512.f * 512.f);
    const float i256 = 1.f / (256.f * 256.f);
    const float i128 = 1.f / (128.f * 128.f);
    const float i64  = 1.f / (64.f * 64.f);
    const float i32  = 1.f / (32.f * 32.f);

    // conv0: [4,3,512,512] -> [4,16,512,512]  (256 partials/plane -> psA)
    conv7_first<<<dim3(256, BB), 256>>>(input, w0, b0, bufA, psA);

    // Block-count-first tiling: every layer >= 512 blocks.
    conv_s2_t<16, 32, 8, 2, 512, 512, 256><<<dim3(64, BB * 4), 256>>>(bufA, w1, b1, bufB, psA, psB, 256, i512);
    conv_s2_t<32, 64, 8, 2, 256, 256, 256><<<dim3(16, BB * 8), 256>>>(bufB, w2, b2, bufA, psB, psA, 64, i256);
    conv_s2_t<64, 128, 4, 2, 128, 128, 256><<<dim3(4, BB * 32), 256>>>(bufA, w3, b3, bufB, psA, psB, 16, i128);
    conv_s2_t<128, 256, 4, 2, 64, 64, 128><<<dim3(2, BB * 64), 128>>>(bufB, w4, b4, bufA, psB, psA, 4, i64);

    deconv_t<256, 128, 4, 2, 32, 32, 256><<<dim3(4, BB * 32), 256>>>(bufA, w5, b5, bufB, psA, psB, 2, i32);
    deconv_t<128, 64, 8, 2, 64, 64, 256><<<dim3(16, BB * 8), 256>>>(bufB, w6, b6, bufA, psB, psA, 4, i64);
    deconv_t<64, 32, 8, 2, 128, 128, 256><<<dim3(64, BB * 4), 256>>>(bufA, w7, b7, bufB, psA, psB, 16, i128);
    deconv_t<32, 16, 8, 2, 256, 256, 256><<<dim3(256, BB * 2), 256>>>(bufB, w8, b8, bufA, psB, psA, 64, i256);

    // conv9 + tanh: [4,16,512,512] -> [4,3,512,512]
    conv7_last<<<dim3(128, BB), 256>>>(bufA, w9, b9, bufB, psA, 256, i512);

    // segment mean + gather
    segpart_k<<<dim3(NUM_INST, 8), 256>>>(bufB, inst);
    segfin_k<<<1, 32>>>();
    gather_k<<<(BB * HH * WW / 4 + 255) / 256, 256>>>(inst, out);
}

// round 13
// speedup vs baseline: 1.0473x; 1.0473x over previous
#include <cuda_runtime.h>
#include <math.h>

#define BB 4
#define HH 512
#define WW 512
#define NUM_INST 32
#define EPS 1e-5f
#define MAXB 256

// Ping-pong activation buffers (max 4*16*512*512 floats = 64MB each)
__device__ float g_bufA[BB * 16 * HH * WW];
__device__ float g_bufB[BB * 16 * HH * WW];
// Ping-pong per-(plane,block) stats partials (sum, sumsq)
__device__ float2 g_psA[BB * 256 * MAXB];
__device__ float2 g_psB[BB * 256 * MAXB];
__device__ float g_means[NUM_INST * 3];
__device__ float g_part[NUM_INST * 8 * 4];

__device__ __forceinline__ int refl(int i, int n) {
    return i < 0 ? -i : (i >= n ? 2 * n - 2 - i : i);
}

// ---------------------------------------------------------------------------
// 3x3 stride-2 conv, zero pad 1, TS=2 specialized. InstanceNorm+ReLU fused on
// the INPUT (stats finalized in-block from psIn partials); fused stats
// partials on OUTPUT into psOut. Thread = 2x2 outputs x COPT channels.
// FLAT inner loop: per ci, one unrolled 25-load x batch (high MLP), then a
// fully-unrolled tap loop with 9*V LDS.128 weight loads and no loop ALU.
// ---------------------------------------------------------------------------
template <int CIN, int COUT, int COPT, int HIN, int WIN, int NT>
__global__ void __launch_bounds__(NT) conv_s2_t(const float* __restrict__ x,
                                                const float* __restrict__ w,
                                                const float* __restrict__ bias,
                                                float* __restrict__ y,
                                                const float2* __restrict__ psIn,
                                                float2* __restrict__ psOut,
                                                int nblkPrev, float invHW) {
    constexpr int HOUT = HIN / 2, WOUT = WIN / 2;
    constexpr int TW = WOUT / 2;
    constexpr int CHUNK = (CIN < 64) ? CIN : 64;
    constexpr int V = COPT / 4;
    __shared__ __align__(16) float wsm[CHUNK * 9 * COPT];
    __shared__ float ssm[NT / 32][COPT], qsm[NT / 32][COPT];
    __shared__ float mnS[CIN], rsS[CIN];

    int t = blockIdx.x * NT + threadIdx.x;
    int cog = blockIdx.y % (COUT / COPT);
    int n = blockIdx.y / (COUT / COPT);
    int oh0 = (t / TW) * 2, ow0 = (t % TW) * 2;
    int lane = threadIdx.x & 31, wrp = threadIdx.x >> 5;

    // Inline finalize of previous layer's stats (deterministic).
    for (int pl = wrp; pl < CIN; pl += NT / 32) {
        float s = 0.f, q = 0.f;
        const float2* pp = psIn + (size_t)(n * CIN + pl) * MAXB;
        for (int i = lane; i < nblkPrev; i += 32) {
            float2 v = pp[i];
            s += v.x;
            q += v.y;
        }
        for (int o = 16; o; o >>= 1) {
            s += __shfl_down_sync(0xffffffffu, s, o);
            q += __shfl_down_sync(0xffffffffu, q, o);
        }
        if (lane == 0) {
            float m = s * invHW;
            float var = q * invHW - m * m;
            mnS[pl] = m;
            rsS[pl] = rsqrtf(var + EPS);
        }
    }
    __syncthreads();

    int iwv[5]; bool cvl[5];
#pragma unroll
    for (int c = 0; c < 5; c++) {
        int iw = ow0 * 2 - 1 + c;
        iwv[c] = iw;
        cvl[c] = (unsigned)iw < (unsigned)WIN;
    }
    int ihv[5]; bool rvl[5];
#pragma unroll
    for (int r = 0; r < 5; r++) {
        int ih = oh0 * 2 - 1 + r;
        ihv[r] = ih;
        rvl[r] = (unsigned)ih < (unsigned)HIN;
    }

    float acc[4 * COPT];
#pragma unroll
    for (int i = 0; i < 4 * COPT; i++) acc[i] = 0.f;

#pragma unroll 1
    for (int c0 = 0; c0 < CIN; c0 += CHUNK) {
        __syncthreads();
        for (int i = threadIdx.x; i < CHUNK * 9 * COPT; i += NT) {
            int ci_l = i / (9 * COPT);
            int rem = i - ci_l * (9 * COPT);
            int tap = rem / COPT;
            int u = rem - tap * COPT;
            wsm[i] = w[((size_t)(cog * COPT + u) * CIN + c0 + ci_l) * 9 + tap];
        }
        __syncthreads();
#pragma unroll 1
        for (int ci_l = 0; ci_l < CHUNK; ci_l++) {
            int ci = c0 + ci_l;
            const float* xp = x + (size_t)(n * CIN + ci) * HIN * WIN;
            float rs = rsS[ci];
            float nb = -mnS[ci] * rs;

            // flat 25-load x batch (normalized + ReLU applied)
            float xv[25];
#pragma unroll
            for (int r = 0; r < 5; r++) {
                const float* xr = xp + (size_t)ihv[r] * WIN;
#pragma unroll
                for (int c = 0; c < 5; c++) {
                    bool v = rvl[r] && cvl[c];
                    float raw = v ? xr[iwv[c]] : 0.f;
                    xv[r * 5 + c] = v ? fmaxf(fmaf(raw, rs, nb), 0.f) : 0.f;
                }
            }

            // flat tap loop: 9*V LDS.128, 36*COPT FMA, zero loop ALU
            const float4* wp4 = reinterpret_cast<const float4*>(wsm + ci_l * 9 * COPT);
#pragma unroll
            for (int kh = 0; kh < 3; kh++) {
#pragma unroll
                for (int kw = 0; kw < 3; kw++) {
#pragma unroll
                    for (int v = 0; v < V; v++) {
                        float4 wq = wp4[(kh * 3 + kw) * V + v];
                        float wa[4] = {wq.x, wq.y, wq.z, wq.w};
#pragma unroll
                        for (int j = 0; j < 4; j++) {
#pragma unroll
                            for (int orow = 0; orow < 2; orow++) {
#pragma unroll
                                for (int oc = 0; oc < 2; oc++) {
                                    acc[(orow * 2 + oc) * COPT + v * 4 + j] =
                                        fmaf(xv[(2 * orow + kh) * 5 + 2 * oc + kw], wa[j],
                                             acc[(orow * 2 + oc) * COPT + v * 4 + j]);
                                }
                            }
                        }
                    }
                }
            }
        }
    }
    // bias
#pragma unroll
    for (int u = 0; u < COPT; u++) {
        float bv = bias[cog * COPT + u];
#pragma unroll
        for (int p = 0; p < 4; p++) acc[p * COPT + u] += bv;
    }
    // stores
    size_t obase = (size_t)(n * COUT + cog * COPT) * HOUT * WOUT + (size_t)oh0 * WOUT + ow0;
#pragma unroll
    for (int u = 0; u < COPT; u++) {
#pragma unroll
        for (int orow = 0; orow < 2; orow++) {
            float* yp = y + obase + (size_t)u * HOUT * WOUT + (size_t)orow * WOUT;
            float2 v;
            v.x = acc[(orow * 2 + 0) * COPT + u];
            v.y = acc[(orow * 2 + 1) * COPT + u];
            *reinterpret_cast<float2*>(yp) = v;
        }
    }
    // fused stats partial (deterministic)
#pragma unroll
    for (int u = 0; u < COPT; u++) {
        float s = 0.f, q = 0.f;
#pragma unroll
        for (int p = 0; p < 4; p++) {
            float v = acc[p * COPT + u];
            s += v;
            q += v * v;
        }
        for (int o = 16; o; o >>= 1) {
            s += __shfl_down_sync(0xffffffffu, s, o);
            q += __shfl_down_sync(0xffffffffu, q, o);
        }
        if (lane == 0) { ssm[wrp][u] = s; qsm[wrp][u] = q; }
    }
    __syncthreads();
    if (threadIdx.x < COPT) {
        float s = 0.f, q = 0.f;
#pragma unroll
        for (int wpp = 0; wpp < NT / 32; wpp++) { s += ssm[wpp][threadIdx.x]; q += qsm[wpp][threadIdx.x]; }
        int plane = n * COUT + cog * COPT + threadIdx.x;
        psOut[(size_t)plane * MAXB + blockIdx.x] = make_float2(s, q);
    }
}

// ---------------------------------------------------------------------------
// ConvTranspose2d k=3 s=2 p=1 op=1, fused norm+relu on input (inline stats),
// fused stats on output. Weight layout (CIN, COUT, 3, 3). TS x TS tile.
// ---------------------------------------------------------------------------
template <int CIN, int COUT, int COPT, int TS, int HIN, int WIN, int NT>
__global__ void __launch_bounds__(NT) deconv_t(const float* __restrict__ x,
                                               const float* __restrict__ w,
                                               const float* __restrict__ bias,
                                               float* __restrict__ y,
                                               const float2* __restrict__ psIn,
                                               float2* __restrict__ psOut,
                                               int nblkPrev, float invHW) {
    constexpr int HOUT = HIN * 2, WOUT = WIN * 2;
    constexpr int TW = WOUT / TS;
    constexpr int SUB = TS / 2;
    constexpr int CHUNK = (CIN < 64) ? CIN : 64;
    constexpr int V = COPT / 4;
    __shared__ __align__(16) float wsm[CHUNK * 9 * COPT];
    __shared__ float ssm[NT / 32][COPT], qsm[NT / 32][COPT];
    __shared__ float mnS[CIN], rsS[CIN];

    int t = blockIdx.x * NT + threadIdx.x;
    int cog = blockIdx.y % (COUT / COPT);
    int n = blockIdx.y / (COUT / COPT);
    int oh0 = (t / TW) * TS, ow0 = (t % TW) * TS;
    int i0 = oh0 >> 1, j0 = ow0 >> 1;
    int lane = threadIdx.x & 31, wrp = threadIdx.x >> 5;

    for (int pl = wrp; pl < CIN; pl += NT / 32) {
        float s = 0.f, q = 0.f;
        const float2* pp = psIn + (size_t)(n * CIN + pl) * MAXB;
        for (int i = lane; i < nblkPrev; i += 32) {
            float2 v = pp[i];
            s += v.x;
            q += v.y;
        }
        for (int o = 16; o; o >>= 1) {
            s += __shfl_down_sync(0xffffffffu, s, o);
            q += __shfl_down_sync(0xffffffffu, q, o);
        }
        if (lane == 0) {
            float m = s * invHW;
            float var = q * invHW - m * m;
            mnS[pl] = m;
            rsS[pl] = rsqrtf(var + EPS);
        }
    }
    __syncthreads();

    float acc[TS * TS * COPT];
#pragma unroll
    for (int i = 0; i < TS * TS * COPT; i++) acc[i] = 0.f;

#pragma unroll 1
    for (int c0 = 0; c0 < CIN; c0 += CHUNK) {
        __syncthreads();
        for (int i = threadIdx.x; i < CHUNK * 9 * COPT; i += NT) {
            int ci_l = i / (9 * COPT);
            int rem = i - ci_l * (9 * COPT);
            int tap = rem / COPT;
            int u = rem - tap * COPT;
            wsm[i] = w[((size_t)(c0 + ci_l) * COUT + cog * COPT + u) * 9 + tap];
        }
        __syncthreads();
#pragma unroll 1
        for (int ci_l = 0; ci_l < CHUNK; ci_l++) {
            int ci = c0 + ci_l;
            const float* xp = x + (size_t)(n * CIN + ci) * HIN * WIN;
            float rs = rsS[ci];
            float nb = -mnS[ci] * rs;
            float xr[(SUB + 1) * (SUB + 1)];
#pragma unroll
            for (int r = 0; r <= SUB; r++) {
                bool rv = (i0 + r) < HIN;
                const float* xpr = xp + (size_t)(i0 + r) * WIN;
#pragma unroll
                for (int c = 0; c <= SUB; c++) {
                    bool v = rv && (j0 + c) < WIN;
                    float raw = v ? xpr[j0 + c] : 0.f;
                    xr[r * (SUB + 1) + c] = v ? fmaxf(fmaf(raw, rs, nb), 0.f) : 0.f;
                }
            }
#pragma unroll
            for (int kh = 0; kh < 3; kh++) {
                int orl = (kh == 1) ? 0 : 1;
                int xro = (kh == 0) ? 1 : 0;
#pragma unroll
                for (int kw = 0; kw < 3; kw++) {
                    int ocl = (kw == 1) ? 0 : 1;
                    int xco = (kw == 0) ? 1 : 0;
                    const float4* wp4 =
                        reinterpret_cast<const float4*>(wsm + (ci_l * 9 + kh * 3 + kw) * COPT);
#pragma unroll
                    for (int v = 0; v < V; v++) {
                        float4 wq = wp4[v];
                        float wa[4] = {wq.x, wq.y, wq.z, wq.w};
#pragma unroll
                        for (int j = 0; j < 4; j++) {
#pragma unroll
                            for (int a = 0; a < SUB; a++)
#pragma unroll
                                for (int b = 0; b < SUB; b++)
                                    acc[((2 * a + orl) * TS + (2 * b + ocl)) * COPT + v * 4 + j] =
                                        fmaf(xr[(a + xro) * (SUB + 1) + (b + xco)], wa[j],
                                             acc[((2 * a + orl) * TS + (2 * b + ocl)) * COPT + v * 4 + j]);
                        }
                    }
                }
            }
        }
    }
#pragma unroll
    for (int u = 0; u < COPT; u++) {
        float bv = bias[cog * COPT + u];
#pragma unroll
        for (int p = 0; p < TS * TS; p++) acc[p * COPT + u] += bv;
    }
    size_t obase = (size_t)(n * COUT + cog * COPT) * HOUT * WOUT + (size_t)oh0 * WOUT + ow0;
#pragma unroll
    for (int u = 0; u < COPT; u++) {
#pragma unroll
        for (int orow = 0; orow < TS; orow++) {
            float* yp = y + obase + (size_t)u * HOUT * WOUT + (size_t)orow * WOUT;
            if (TS == 4) {
                float4 v;
                v.x = acc[(orow * TS + 0) * COPT + u];
                v.y = acc[(orow * TS + 1) * COPT + u];
                v.z = acc[(orow * TS + 2) * COPT + u];
                v.w = acc[(orow * TS + 3) * COPT + u];
                *reinterpret_cast<float4*>(yp) = v;
            } else {
                float2 v;
                v.x = acc[(orow * TS + 0) * COPT + u];
                v.y = acc[(orow * TS + 1) * COPT + u];
                *reinterpret_cast<float2*>(yp) = v;
            }
        }
    }
#pragma unroll
    for (int u = 0; u < COPT; u++) {
        float s = 0.f, q = 0.f;
#pragma unroll
        for (int p = 0; p < TS * TS; p++) {
            float v = acc[p * COPT + u];
            s += v;
            q += v * v;
        }
        for (int o = 16; o; o >>= 1) {
            s += __shfl_down_sync(0xffffffffu, s, o);
            q += __shfl_down_sync(0xffffffffu, q, o);
        }
        if (lane == 0) { ssm[wrp][u] = s; qsm[wrp][u] = q; }
    }
    __syncthreads();
    if (threadIdx.x < COPT) {
        float s = 0.f, q = 0.f;
#pragma unroll
        for (int wpp = 0; wpp < NT / 32; wpp++) { s += ssm[wpp][threadIdx.x]; q += qsm[wpp][threadIdx.x]; }
        int plane = n * COUT + cog * COPT + threadIdx.x;
        psOut[(size_t)plane * MAXB + blockIdx.x] = make_float2(s, q);
    }
}

// ---------------------------------------------------------------------------
// conv0: reflect-pad 3, 7x7, 3->16. Thread = 1 row x 4 cols, all 16 co.
// Interior threads use 3x LDG.128 for the 10-wide footprint row.
// ---------------------------------------------------------------------------
__global__ void __launch_bounds__(256) conv7_first(const float* __restrict__ x,
                                                   const float* __restrict__ w,
                                                   const float* __restrict__ bias,
                                                   float* __restrict__ y,
                                                   float2* __restrict__ psOut) {
    __shared__ __align__(16) float wsm[3 * 49 * 16];
    __shared__ float ssm[8][16], qsm[8][16];
    for (int i = threadIdx.x; i < 3 * 49 * 16; i += 256) {
        int ci = i / (49 * 16);
        int rem = i - ci * (49 * 16);
        int tap = rem / 16;
        int co = rem - tap * 16;
        wsm[i] = w[(co * 3 + ci) * 49 + tap];
    }
    __syncthreads();

    int t = blockIdx.x * 256 + threadIdx.x;
    int n = blockIdx.y;
    int oh = t >> 7;               // 128 threads per row, 4 px each
    int ow0 = (t & 127) * 4;

    int iwI[10];
#pragma unroll
    for (int c = 0; c < 10; c++) iwI[c] = refl(ow0 - 3 + c, WW);
    bool wInt = (ow0 >= 4) && (ow0 + 7 <= WW - 1);

    float acc[4 * 16];
#pragma unroll
    for (int i = 0; i < 4 * 16; i++) acc[i] = 0.f;

#pragma unroll 1
    for (int ci = 0; ci < 3; ci++) {
        const float* xp = x + (size_t)(n * 3 + ci) * HH * WW;
#pragma unroll 1
        for (int kh = 0; kh < 7; kh++) {
            const float* xr = xp + (size_t)refl(oh + kh - 3, HH) * WW;
            float xv[10];
            if (wInt) {
                const float* b = xr + ow0;
                float4 qa = *reinterpret_cast<const float4*>(b - 4);
                float4 qb = *reinterpret_cast<const float4*>(b);
                float4 qc = *reinterpret_cast<const float4*>(b + 4);
                xv[0] = qa.y; xv[1] = qa.z; xv[2] = qa.w;
                xv[3] = qb.x; xv[4] = qb.y; xv[5] = qb.z; xv[6] = qb.w;
                xv[7] = qc.x; xv[8] = qc.y; xv[9] = qc.z;
            } else {
#pragma unroll
                for (int c = 0; c < 10; c++) xv[c] = xr[iwI[c]];
            }
            const float4* wb4 = reinterpret_cast<const float4*>(wsm + (ci * 49 + kh * 7) * 16);
#pragma unroll
            for (int kw = 0; kw < 7; kw++) {
#pragma unroll
                for (int v = 0; v < 4; v++) {
                    float4 wq = wb4[kw * 4 + v];
                    float wa[4] = {wq.x, wq.y, wq.z, wq.w};
#pragma unroll
                    for (int j = 0; j < 4; j++) {
#pragma unroll
                        for (int sc = 0; sc < 4; sc++)
                            acc[sc * 16 + v * 4 + j] = fmaf(xv[sc + kw], wa[j], acc[sc * 16 + v * 4 + j]);
                    }
                }
            }
        }
    }
#pragma unroll
    for (int co = 0; co < 16; co++) {
        float bv = bias[co];
#pragma unroll
        for (int sc = 0; sc < 4; sc++) acc[sc * 16 + co] += bv;
    }
#pragma unroll
    for (int co = 0; co < 16; co++) {
        float* yp = y + (size_t)(n * 16 + co) * HH * WW + (size_t)oh * WW + ow0;
        float4 v0;
        v0.x = acc[0 * 16 + co]; v0.y = acc[1 * 16 + co];
        v0.z = acc[2 * 16 + co]; v0.w = acc[3 * 16 + co];
        *reinterpret_cast<float4*>(yp) = v0;
    }
    int lane = threadIdx.x & 31, wrp = threadIdx.x >> 5;
#pragma unroll
    for (int co = 0; co < 16; co++) {
        float s = 0.f, q = 0.f;
#pragma unroll
        for (int sc = 0; sc < 4; sc++) {
            float v = acc[sc * 16 + co];
            s += v;
            q += v * v;
        }
        for (int o = 16; o; o >>= 1) {
            s += __shfl_down_sync(0xffffffffu, s, o);
            q += __shfl_down_sync(0xffffffffu, q, o);
        }
        if (lane == 0) { ssm[wrp][co] = s; qsm[wrp][co] = q; }
    }
    __syncthreads();
    if (threadIdx.x < 16) {
        float s = 0.f, q = 0.f;
#pragma unroll
        for (int wpp = 0; wpp < 8; wpp++) { s += ssm[wpp][threadIdx.x]; q += qsm[wpp][threadIdx.x]; }
        int plane = n * 16 + threadIdx.x;
        psOut[(size_t)plane * MAXB + blockIdx.x] = make_float2(s, q);
    }
}

// ---------------------------------------------------------------------------
// conv9: reflect-pad 3, 7x7, 16->3, inline-stats norm+relu on input, tanh out.
// Interior threads use 4x LDG.128 for the 14-wide footprint row.
// ---------------------------------------------------------------------------
__global__ void __launch_bounds__(256) conv7_last(const float* __restrict__ x,
                                                  const float* __restrict__ w,
                                                  const float* __restrict__ bias,
                                                  float* __restrict__ y,
                                                  const float2* __restrict__ psIn,
                                                  int nblkPrev, float invHW) {
    __shared__ float wsm[16 * 49 * 3];
    __shared__ float mnS[16], rsS[16];
    for (int i = threadIdx.x; i < 16 * 49 * 3; i += 256) {
        int ci = i / (49 * 3);
        int rem = i - ci * (49 * 3);
        int tap = rem / 3;
        int co = rem - tap * 3;
        wsm[i] = w[(co * 16 + ci) * 49 + tap];
    }
    int lane = threadIdx.x & 31, wrp = threadIdx.x >> 5;
    int n = blockIdx.y;
    for (int pl = wrp; pl < 16; pl += 8) {
        float s = 0.f, q = 0.f;
        const float2* pp = psIn + (size_t)(n * 16 + pl) * MAXB;
        for (int i = lane; i < nblkPrev; i += 32) {
            float2 v = pp[i];
            s += v.x;
            q += v.y;
        }
        for (int o = 16; o; o >>= 1) {
            s += __shfl_down_sync(0xffffffffu, s, o);
            q += __shfl_down_sync(0xffffffffu, q, o);
        }
        if (lane == 0) {
            float m = s * invHW;
            float var = q * invHW - m * m;
            mnS[pl] = m;
            rsS[pl] = rsqrtf(var + EPS);
        }
    }
    __syncthreads();

    int t = blockIdx.x * 256 + threadIdx.x;
    int oh = t >> 6;
    int ow0 = (t & 63) * 8;

    int iwI[14];
#pragma unroll
    for (int c = 0; c < 14; c++) iwI[c] = refl(ow0 - 3 + c, WW);
    bool wInt = (ow0 >= 8) && (ow0 + 11 <= WW - 1);

    float acc[8 * 3];
#pragma unroll
    for (int i = 0; i < 8 * 3; i++) acc[i] = 0.f;

#pragma unroll 1
    for (int ci = 0; ci < 16; ci++) {
        const float* xp = x + (size_t)(n * 16 + ci) * HH * WW;
        float rs = rsS[ci];
        float nb = -mnS[ci] * rs;
#pragma unroll 1
        for (int kh = 0; kh < 7; kh++) {
            const float* xr = xp + (size_t)refl(oh + kh - 3, HH) * WW;
            float xv[14];
            if (wInt) {
                const float* b = xr + ow0;
                float4 qa = *reinterpret_cast<const float4*>(b - 4);
                float4 qb = *reinterpret_cast<const float4*>(b);
                float4 qc = *reinterpret_cast<const float4*>(b + 4);
                float4 qd = *reinterpret_cast<const float4*>(b + 8);
                xv[0] = qa.y;  xv[1] = qa.z;  xv[2] = qa.w;
                xv[3] = qb.x;  xv[4] = qb.y;  xv[5] = qb.z;  xv[6] = qb.w;
                xv[7] = qc.x;  xv[8] = qc.y;  xv[9] = qc.z;  xv[10] = qc.w;
                xv[11] = qd.x; xv[12] = qd.y; xv[13] = qd.z;
            } else {
#pragma unroll
                for (int c = 0; c < 14; c++) xv[c] = xr[iwI[c]];
            }
#pragma unroll
            for (int c = 0; c < 14; c++) xv[c] = fmaxf(fmaf(xv[c], rs, nb), 0.f);
            const float* wb = wsm + (ci * 49 + kh * 7) * 3;
#pragma unroll
            for (int kw = 0; kw < 7; kw++) {
#pragma unroll
                for (int co = 0; co < 3; co++) {
                    float wvv = wb[kw * 3 + co];
#pragma unroll
                    for (int sc = 0; sc < 8; sc++)
                        acc[sc * 3 + co] = fmaf(xv[sc + kw], wvv, acc[sc * 3 + co]);
                }
            }
        }
    }
#pragma unroll
    for (int co = 0; co < 3; co++) {
        float bv = bias[co];
        float* yp = y + (size_t)(n * 3 + co) * HH * WW + (size_t)oh * WW + ow0;
        float4 v0, v1;
        v0.x = tanhf(acc[0 * 3 + co] + bv); v0.y = tanhf(acc[1 * 3 + co] + bv);
        v0.z = tanhf(acc[2 * 3 + co] + bv); v0.w = tanhf(acc[3 * 3 + co] + bv);
        v1.x = tanhf(acc[4 * 3 + co] + bv); v1.y = tanhf(acc[5 * 3 + co] + bv);
        v1.z = tanhf(acc[6 * 3 + co] + bv); v1.w = tanhf(acc[7 * 3 + co] + bv);
        ((float4*)yp)[0] = v0;
        ((float4*)yp)[1] = v1;
    }
}

// ---------------------------------------------------------------------------
// Segment mean: (label, slice) partials, deterministic, then combine.
// ---------------------------------------------------------------------------
__global__ void segpart_k(const float* __restrict__ feats, const int* __restrict__ inst) {
    int lab = blockIdx.x, slice = blockIdx.y;
    const int HWp = HH * WW;
    const int per = BB * HWp / 8;
    int start = slice * per;
    float c0 = 0.f, c1 = 0.f, c2 = 0.f, cnt = 0.f;
    for (int p = start + threadIdx.x; p < start + per; p += 256) {
        if (inst[p] == lab) {
            int n = p / HWp;
            int hw = p - n * HWp;
            const float* f = feats + (size_t)n * 3 * HWp + hw;
            c0 += f[0];
            c1 += f[HWp];
            c2 += f[2 * HWp];
            cnt += 1.f;
        }
    }
    __shared__ float s0[256], s1[256], s2[256], sc[256];
    s0[threadIdx.x] = c0; s1[threadIdx.x] = c1; s2[threadIdx.x] = c2; sc[threadIdx.x] = cnt;
    __syncthreads();
    for (int o = 128; o > 0; o >>= 1) {
        if (threadIdx.x < o) {
            s0[threadIdx.x] += s0[threadIdx.x + o];
            s1[threadIdx.x] += s1[threadIdx.x + o];
            s2[threadIdx.x] += s2[threadIdx.x + o];
            sc[threadIdx.x] += sc[threadIdx.x + o];
        }
        __syncthreads();
    }
    if (threadIdx.x == 0) {
        float* q = &g_part[(lab * 8 + slice) * 4];
        q[0] = s0[0]; q[1] = s1[0]; q[2] = s2[0]; q[3] = sc[0];
    }
}

__global__ void segfin_k() {
    int lab = threadIdx.x;
    if (lab >= NUM_INST) return;
    float s0 = 0.f, s1 = 0.f, s2 = 0.f, c = 0.f;
    for (int sl = 0; sl < 8; sl++) {
        const float* p = &g_part[(lab * 8 + sl) * 4];
        s0 += p[0]; s1 += p[1]; s2 += p[2]; c += p[3];
    }
    float d = fmaxf(c, 1.f);
    g_means[lab * 3 + 0] = s0 / d;
    g_means[lab * 3 + 1] = s1 / d;
    g_means[lab * 3 + 2] = s2 / d;
}

__global__ void gather_k(const int* __restrict__ inst, float* __restrict__ out) {
    int idx = blockIdx.x * 256 + threadIdx.x;
    const int Q = HH * WW / 4;
    if (idx >= BB * Q) return;
    int n = idx / Q, h4 = idx - n * Q;
    int4 lb = ((const int4*)inst)[(size_t)n * Q + h4];
#pragma unroll
    for (int c = 0; c < 3; c++) {
        float4 v;
        v.x = g_means[lb.x * 3 + c];
        v.y = g_means[lb.y * 3 + c];
        v.z = g_means[lb.z * 3 + c];
        v.w = g_means[lb.w * 3 + c];
        ((float4*)out)[(size_t)(n * 3 + c) * Q + h4] = v;
    }
}

// ---------------------------------------------------------------------------
extern "C" void kernel_launch(void* const* d_in, const int* in_sizes, int n_in,
                              void* d_out, int out_size) {
    const float* input = (const float*)d_in[0];
    const int* inst = (const int*)d_in[1];
    const float* w0 = (const float*)d_in[2];  const float* b0 = (const float*)d_in[3];
    const float* w1 = (const float*)d_in[4];  const float* b1 = (const float*)d_in[5];
    const float* w2 = (const float*)d_in[6];  const float* b2 = (const float*)d_in[7];
    const float* w3 = (const float*)d_in[8];  const float* b3 = (const float*)d_in[9];
    const float* w4 = (const float*)d_in[10]; const float* b4 = (const float*)d_in[11];
    const float* w5 = (const float*)d_in[12]; const float* b5 = (const float*)d_in[13];
    const float* w6 = (const float*)d_in[14]; const float* b6 = (const float*)d_in[15];
    const float* w7 = (const float*)d_in[16]; const float* b7 = (const float*)d_in[17];
    const float* w8 = (const float*)d_in[18]; const float* b8 = (const float*)d_in[19];
    const float* w9 = (const float*)d_in[20]; const float* b9 = (const float*)d_in[21];
    float* out = (float*)d_out;

    float* bufA;
    float* bufB;
    float2* psA;
    float2* psB;
    cudaGetSymbolAddress((void**)&bufA, g_bufA);
    cudaGetSymbolAddress((void**)&bufB, g_bufB);
    cudaGetSymbolAddress((void**)&psA, g_psA);
    cudaGetSymbolAddress((void**)&psB, g_psB);

    const float i512 = 1.f / (512.f * 512.f);
    const float i256 = 1.f / (256.f * 256.f);
    const float i128 = 1.f / (128.f * 128.f);
    const float i64  = 1.f / (64.f * 64.f);
    const float i32  = 1.f / (32.f * 32.f);

    // conv0: [4,3,512,512] -> [4,16,512,512]  (256 partials/plane -> psA)
    conv7_first<<<dim3(256, BB), 256>>>(input, w0, b0, bufA, psA);

    // Flat-inner-loop stride-2 convs.
    conv_s2_t<16, 32, 8, 512, 512, 256><<<dim3(64, BB * 4), 256>>>(bufA, w1, b1, bufB, psA, psB, 256, i512);
    conv_s2_t<32, 64, 8, 256, 256, 256><<<dim3(16, BB * 8), 256>>>(bufB, w2, b2, bufA, psB, psA, 64, i256);
    conv_s2_t<64, 128, 4, 128, 128, 256><<<dim3(4, BB * 32), 256>>>(bufA, w3, b3, bufB, psA, psB, 16, i128);
    conv_s2_t<128, 256, 4, 64, 64, 256><<<dim3(1, BB * 64), 256>>>(bufB, w4, b4, bufA, psB, psA, 4, i64);

    deconv_t<256, 128, 4, 2, 32, 32, 256><<<dim3(4, BB * 32), 256>>>(bufA, w5, b5, bufB, psA, psB, 1, i32);
    deconv_t<128, 64, 8, 2, 64, 64, 256><<<dim3(16, BB * 8), 256>>>(bufB, w6, b6, bufA, psB, psA, 4, i64);
    deconv_t<64, 32, 8, 2, 128, 128, 256><<<dim3(64, BB * 4), 256>>>(bufA, w7, b7, bufB, psA, psB, 16, i128);
    deconv_t<32, 16, 8, 2, 256, 256, 256><<<dim3(256, BB * 2), 256>>>(bufB, w8, b8, bufA, psB, psA, 64, i256);

    // conv9 + tanh: [4,16,512,512] -> [4,3,512,512]
    conv7_last<<<dim3(128, BB), 256>>>(bufA, w9, b9, bufB, psA, 256, i512);

    // segment mean + gather
    segpart_k<<<dim3(NUM_INST, 8), 256>>>(bufB, inst);
    segfin_k<<<1, 32>>>();
    gather_k<<<(BB * HH * WW / 4 + 255) / 256, 256>>>(inst, out);
}